// round 15
// baseline (speedup 1.0000x reference)
#include <cuda_runtime.h>
#include <cuda_fp16.h>
#include <mma.h>
#include <math.h>

using namespace nvcuda;

// Problem constants (fixed-shape problem)
#define BB   16
#define NN   2048
#define DD   64
#define EE   32768
#define MAXK 128
#define ROWS (BB*NN)          // 32768
#define TBL  128
#define BR   64               // rows per gemm block

// Scratch (device globals; zero-initialized at module load; no allocation)
__device__ int      g_cnt_raw[ROWS];                 // scatter counters (reset by dedup)
__device__ int      g_nnz[ROWS];                     // padded row sizes (multiple of 8)
__device__ uint2    g_bucket[(size_t)ROWS * MAXK];   // 32 MB (col<<17|pri, m_bits)
__device__ float    g_dis[ROWS];
__device__ uint2    g_adj[(size_t)ROWS * MAXK];      // 32 MB (col<<7 byte-off, m_bits)
__device__ __half2  g_x [(size_t)ROWS * 32];         // 4 MB: dis ⊙ H   (layer 0 input)
__device__ __half2  g_x1[(size_t)ROWS * 32];         // 4 MB: dis ⊙ x1  (layer 1 input)
__device__ __half2  g_pre[(size_t)ROWS * 32];        // 4 MB: fp16 dis_r*(A·X~ + X~row)
__device__ __half   g_wh[2 * 64 * 64];               // fp16 W, both layers

// ---------------------------------------------------------------------------
// scatter directed entries into per-row buckets, carrying m (coalesced read).
// key = (col << 17) | priority, priority = pass*E + e (pass2 > pass1).
// Threads t < 8192 also convert W to fp16 (both layers) for the wmma GEMM.
__global__ void scatter_k(const int* __restrict__ ei, const float* __restrict__ m,
                          const float* __restrict__ Wf) {
    int t = blockIdx.x * blockDim.x + threadIdx.x;
    if (t < 2 * 64 * 64) g_wh[t] = __float2half(Wf[t]);

    int b = t >> 15;
    int e = t & (EE - 1);
    int src = ei[b * 2 * EE + e];
    int dst = ei[b * 2 * EE + EE + e];
    unsigned mbits = __float_as_uint(m[t]);

    int r1 = b * NN + src;
    int p1 = atomicAdd(&g_cnt_raw[r1], 1);
    if (p1 < MAXK)
        g_bucket[(size_t)r1 * MAXK + p1] = make_uint2(((unsigned)dst << 17) | (unsigned)e, mbits);

    int r2 = b * NN + dst;
    int p2 = atomicAdd(&g_cnt_raw[r2], 1);
    if (p2 < MAXK)
        g_bucket[(size_t)r2 * MAXK + p2] = make_uint2(((unsigned)src << 17) | (unsigned)(EE + e), mbits);
}

// ---------------------------------------------------------------------------
// O(k) hash dedup (exact .set last-write-wins via 64-bit atomicMax on
// (col<<17|pri) in high word), ballot compaction into zero-padded CSR storing
// BYTE OFFSETS (col*128), deg -> dis = rsqrt(deg), AND prep: g_x = half(dis ⊙ H).
// Resets g_cnt_raw. One warp per row, 8 rows per block.
__global__ void __launch_bounds__(256) dedup_k(const float* __restrict__ H) {
    __shared__ unsigned long long tbl[8][TBL];
    int wid  = threadIdx.x >> 5, lane = threadIdx.x & 31;
    int row  = blockIdx.x * 8 + wid;

    for (int i = lane; i < TBL; i += 32) tbl[wid][i] = 0ULL;
    __syncwarp();

    int k = g_cnt_raw[row];
    if (k > MAXK) k = MAXK;
    const uint2* src = &g_bucket[(size_t)row * MAXK];
    for (int t = lane; t < k; t += 32) {
        uint2 v = src[t];
        unsigned col = v.x >> 17;
        unsigned long long val = ((unsigned long long)v.x << 32) | (unsigned long long)v.y;
        unsigned h = col & (TBL - 1);
        while (true) {
            unsigned long long cur = tbl[wid][h];
            if (cur == 0ULL) {
                unsigned long long old = atomicCAS(&tbl[wid][h], 0ULL, val);
                if (old == 0ULL) break;
                cur = old;
            }
            if ((unsigned)(cur >> 49) == col) {       // same col -> keep max priority
                atomicMax(&tbl[wid][h], val);
                break;
            }
            h = (h + 1) & (TBL - 1);
        }
    }
    __syncwarp();

    // compact + degree sum; store byte offset col*128 (fp16 row = 128B)
    float deg = 0.f;
    int base = 0;
    uint2* dst = &g_adj[(size_t)row * MAXK];
    #pragma unroll
    for (int s0 = 0; s0 < TBL; s0 += 32) {
        unsigned long long cur = tbl[wid][s0 + lane];
        bool has = (cur != 0ULL);
        unsigned bal = __ballot_sync(0xFFFFFFFFu, has);
        if (has) {
            int pos = base + __popc(bal & ((1u << lane) - 1));
            unsigned col = ((unsigned)(cur >> 32)) >> 17;
            unsigned mb  = (unsigned)cur;
            dst[pos] = make_uint2(col << 7, mb);
            deg += __uint_as_float(mb);
        }
        base += __popc(bal);
    }
    // zero padding up to multiple of 8 (beyond stays zero from static init;
    // replays rewrite identical data so zero region is invariant)
    int pad = (base + 7) & ~7;
    if (base + lane < pad) dst[base + lane] = make_uint2(0u, 0u);

    // all-lanes deg reduction -> dis on every lane
    #pragma unroll
    for (int o = 16; o; o >>= 1) deg += __shfl_xor_sync(0xFFFFFFFFu, deg, o);
    float dis = rsqrtf(fmaxf(1.0f + deg, 1e-6f));

    // prep: g_x[row] = half(dis * H[row])
    const float2* Hrow = (const float2*)H + row * 32;
    float2 h2 = Hrow[lane];
    g_x[row * 32 + lane] = __floats2half2_rn(dis * h2.x, dis * h2.y);

    if (lane == 0) {
        g_nnz[row] = pad;
        g_dis[row] = dis;
        g_cnt_raw[row] = 0;     // ready for next replay
    }
}

// ---------------------------------------------------------------------------
// SpMM phase (R10 version): pre[row] = dis_r * (sum_e m_e*X~[col] + X~[row]).
// TWO rows per warp, interleaved in registers; 16 independent gathers + 8
// uniform LDG.128 in flight per warp. Pad entries are (0,0) -> w=0 no-ops.
// Output stored fp16 for the tensor-core GEMM.
__global__ void __launch_bounds__(256) spmm_k(int stage) {
    const __half2* Xin = (stage == 0) ? g_x : g_x1;
    int wid = threadIdx.x >> 5, lane = threadIdx.x & 31;
    int row0 = (blockIdx.x * 8 + wid) * 2;
    int row1 = row0 + 1;

    const char* XbL = (const char*)(Xin + (row0 & ~(NN - 1)) * 32) + lane * 4;
    float2 a0 = __half22float2(Xin[row0 * 32 + lane]);   // diag term X~row0
    float2 a1 = __half22float2(Xin[row1 * 32 + lane]);   // diag term X~row1
    const uint2* ar0 = &g_adj[(size_t)row0 * MAXK];
    const uint2* ar1 = ar0 + MAXK;
    int n = max(g_nnz[row0], g_nnz[row1]);               // <= MAXK, multiple of 8

    for (int k = 0; k < n; k += 8) {
        uint4 e0 = *(const uint4*)(ar0 + k);
        uint4 e1 = *(const uint4*)(ar0 + k + 2);
        uint4 e2 = *(const uint4*)(ar0 + k + 4);
        uint4 e3 = *(const uint4*)(ar0 + k + 6);
        uint4 g0 = *(const uint4*)(ar1 + k);
        uint4 g1 = *(const uint4*)(ar1 + k + 2);
        uint4 g2 = *(const uint4*)(ar1 + k + 4);
        uint4 g3 = *(const uint4*)(ar1 + k + 6);

        __half2 x0 = *(const __half2*)(XbL + e0.x);
        __half2 x1 = *(const __half2*)(XbL + e0.z);
        __half2 x2 = *(const __half2*)(XbL + e1.x);
        __half2 x3 = *(const __half2*)(XbL + e1.z);
        __half2 x4 = *(const __half2*)(XbL + e2.x);
        __half2 x5 = *(const __half2*)(XbL + e2.z);
        __half2 x6 = *(const __half2*)(XbL + e3.x);
        __half2 x7 = *(const __half2*)(XbL + e3.z);
        __half2 y0 = *(const __half2*)(XbL + g0.x);
        __half2 y1 = *(const __half2*)(XbL + g0.z);
        __half2 y2 = *(const __half2*)(XbL + g1.x);
        __half2 y3 = *(const __half2*)(XbL + g1.z);
        __half2 y4 = *(const __half2*)(XbL + g2.x);
        __half2 y5 = *(const __half2*)(XbL + g2.z);
        __half2 y6 = *(const __half2*)(XbL + g3.x);
        __half2 y7 = *(const __half2*)(XbL + g3.z);

        float2 f;
        f = __half22float2(x0); a0.x += __uint_as_float(e0.y) * f.x; a0.y += __uint_as_float(e0.y) * f.y;
        f = __half22float2(x1); a0.x += __uint_as_float(e0.w) * f.x; a0.y += __uint_as_float(e0.w) * f.y;
        f = __half22float2(x2); a0.x += __uint_as_float(e1.y) * f.x; a0.y += __uint_as_float(e1.y) * f.y;
        f = __half22float2(x3); a0.x += __uint_as_float(e1.w) * f.x; a0.y += __uint_as_float(e1.w) * f.y;
        f = __half22float2(x4); a0.x += __uint_as_float(e2.y) * f.x; a0.y += __uint_as_float(e2.y) * f.y;
        f = __half22float2(x5); a0.x += __uint_as_float(e2.w) * f.x; a0.y += __uint_as_float(e2.w) * f.y;
        f = __half22float2(x6); a0.x += __uint_as_float(e3.y) * f.x; a0.y += __uint_as_float(e3.y) * f.y;
        f = __half22float2(x7); a0.x += __uint_as_float(e3.w) * f.x; a0.y += __uint_as_float(e3.w) * f.y;
        f = __half22float2(y0); a1.x += __uint_as_float(g0.y) * f.x; a1.y += __uint_as_float(g0.y) * f.y;
        f = __half22float2(y1); a1.x += __uint_as_float(g0.w) * f.x; a1.y += __uint_as_float(g0.w) * f.y;
        f = __half22float2(y2); a1.x += __uint_as_float(g1.y) * f.x; a1.y += __uint_as_float(g1.y) * f.y;
        f = __half22float2(y3); a1.x += __uint_as_float(g1.w) * f.x; a1.y += __uint_as_float(g1.w) * f.y;
        f = __half22float2(y4); a1.x += __uint_as_float(g2.y) * f.x; a1.y += __uint_as_float(g2.y) * f.y;
        f = __half22float2(y5); a1.x += __uint_as_float(g2.w) * f.x; a1.y += __uint_as_float(g2.w) * f.y;
        f = __half22float2(y6); a1.x += __uint_as_float(g3.y) * f.x; a1.y += __uint_as_float(g3.y) * f.y;
        f = __half22float2(y7); a1.x += __uint_as_float(g3.w) * f.x; a1.y += __uint_as_float(g3.w) * f.y;
    }
    float d0 = g_dis[row0];
    float d1 = g_dis[row1];
    g_pre[row0 * 32 + lane] = __floats2half2_rn(d0 * a0.x, d0 * a0.y);
    g_pre[row1 * 32 + lane] = __floats2half2_rn(d1 * a1.x, d1 * a1.y);
}

// ---------------------------------------------------------------------------
// Tensor-core GEMM, fully warp-independent: NO block syncs, NO W staging.
// Warp = 16-row band x 32-col half (2 wmma tiles, 4 k-steps); A and B
// fragments loaded straight from global (W fp16 pre-converted in scatter_k;
// L1/L2-resident). Stage 1 stores accumulators directly to global fp32.
// Stage 0 stores to a warp-private smem patch (__syncwarp only), then the
// same warp applies exact GELU + dis-prescale and stores fp16.
__global__ void __launch_bounds__(256) gemm_k(float* __restrict__ out, int stage) {
    __shared__ float sOut[8][16 * 36 + 4];
    int w = threadIdx.x >> 5, lane = threadIdx.x & 31;
    int row0 = blockIdx.x * BR;
    int band = w >> 1, ch = w & 1;
    int rband = row0 + band * 16;

    const __half* A  = (const __half*)g_pre + (size_t)rband * 64;  // row-major ld=64
    const __half* Wg = g_wh + stage * 4096;                        // col-major (d,e) ld=64

    wmma::fragment<wmma::accumulator, 16, 16, 16, float> c0, c1;
    wmma::fill_fragment(c0, 0.f);
    wmma::fill_fragment(c1, 0.f);
    #pragma unroll
    for (int k0 = 0; k0 < 4; k0++) {
        wmma::fragment<wmma::matrix_a, 16, 16, 16, __half, wmma::row_major> a;
        wmma::fragment<wmma::matrix_b, 16, 16, 16, __half, wmma::col_major> b0, b1;
        wmma::load_matrix_sync(a, A + k0 * 16, 64);
        wmma::load_matrix_sync(b0, Wg + (ch * 32) * 64 + k0 * 16, 64);
        wmma::load_matrix_sync(b1, Wg + (ch * 32 + 16) * 64 + k0 * 16, 64);
        wmma::mma_sync(c0, a, b0, c0);
        wmma::mma_sync(c1, a, b1, c1);
    }

    if (stage == 1) {
        float* dst = out + (size_t)rband * 64 + ch * 32;
        wmma::store_matrix_sync(dst, c0, 64, wmma::mem_row_major);
        wmma::store_matrix_sync(dst + 16, c1, 64, wmma::mem_row_major);
    } else {
        wmma::store_matrix_sync(&sOut[w][0],  c0, 36, wmma::mem_row_major);
        wmma::store_matrix_sync(&sOut[w][16], c1, 36, wmma::mem_row_major);
        __syncwarp();
        // epilogue: 2 lanes per row, 16 cols each (warp-private data)
        int r = lane >> 1, cb = (lane & 1) * 16;
        int row = rband + r;
        float dis = g_dis[row];
        const float* src = &sOut[w][r * 36 + cb];
        #pragma unroll
        for (int i = 0; i < 8; i++) {
            float vx = src[i * 2], vy = src[i * 2 + 1];
            vx = 0.5f * vx * (1.f + erff(vx * 0.70710678118654752f));
            vy = 0.5f * vy * (1.f + erff(vy * 0.70710678118654752f));
            g_x1[row * 32 + ((ch * 32 + cb) >> 1) + i] = __floats2half2_rn(dis * vx, dis * vy);
        }
    }
}

// ---------------------------------------------------------------------------
extern "C" void kernel_launch(void* const* d_in, const int* in_sizes, int n_in,
                              void* d_out, int out_size) {
    const float* H  = (const float*)d_in[0];
    const int*   ei = (const int*)  d_in[1];
    const float* m  = (const float*)d_in[2];
    const float* W  = (const float*)d_in[3];
    float* out = (float*)d_out;

    scatter_k<<<(BB * EE) / 256, 256>>>(ei, m, W);
    dedup_k<<<ROWS / 8, 256>>>(H);
    spmm_k<<<ROWS / 16, 256>>>(0);                      // g_x  -> g_pre
    gemm_k<<<ROWS / BR, 256>>>(nullptr, 0);             // g_pre -> g_x1 (GELU)
    spmm_k<<<ROWS / 16, 256>>>(1);                      // g_x1 -> g_pre
    gemm_k<<<ROWS / BR, 256>>>(out, 1);                 // g_pre -> out
}

// round 16
// speedup vs baseline: 1.3367x; 1.3367x over previous
#include <cuda_runtime.h>
#include <cuda_fp16.h>
#include <mma.h>
#include <math.h>

using namespace nvcuda;

// Problem constants (fixed-shape problem)
#define BB   16
#define NN   2048
#define DD   64
#define EE   32768
#define MAXK 128
#define ROWS (BB*NN)          // 32768
#define TBL  128
#define BR   64               // rows per gemm chunk
#define GCHUNKS 4             // chunks per gemm block

// Scratch (device globals; zero-initialized at module load; no allocation)
__device__ int      g_cnt_raw[ROWS];                 // scatter counters (reset by dedup)
__device__ int      g_nnz[ROWS];                     // padded row sizes (multiple of 8)
__device__ uint2    g_bucket[(size_t)ROWS * MAXK];   // 32 MB (col<<17|pri, m_bits)
__device__ float    g_dis[ROWS];
__device__ uint2    g_adj[(size_t)ROWS * MAXK];      // 32 MB (col<<7 byte-off, m_bits)
__device__ __half2  g_x [(size_t)ROWS * 32];         // 4 MB: dis ⊙ H   (layer 0 input)
__device__ __half2  g_x1[(size_t)ROWS * 32];         // 4 MB: dis ⊙ x1  (layer 1 input)
__device__ __half2  g_pre[(size_t)ROWS * 32];        // 4 MB: fp16 dis_r*(A·X~ + X~row)

// ---------------------------------------------------------------------------
// scatter directed entries into per-row buckets, carrying m (coalesced read).
// key = (col << 17) | priority, priority = pass*E + e (pass2 > pass1)
__global__ void scatter_k(const int* __restrict__ ei, const float* __restrict__ m) {
    int t = blockIdx.x * blockDim.x + threadIdx.x;
    int b = t >> 15;
    int e = t & (EE - 1);
    int src = ei[b * 2 * EE + e];
    int dst = ei[b * 2 * EE + EE + e];
    unsigned mbits = __float_as_uint(m[t]);

    int r1 = b * NN + src;
    int p1 = atomicAdd(&g_cnt_raw[r1], 1);
    if (p1 < MAXK)
        g_bucket[(size_t)r1 * MAXK + p1] = make_uint2(((unsigned)dst << 17) | (unsigned)e, mbits);

    int r2 = b * NN + dst;
    int p2 = atomicAdd(&g_cnt_raw[r2], 1);
    if (p2 < MAXK)
        g_bucket[(size_t)r2 * MAXK + p2] = make_uint2(((unsigned)src << 17) | (unsigned)(EE + e), mbits);
}

// ---------------------------------------------------------------------------
// O(k) hash dedup (exact .set last-write-wins via 64-bit atomicMax on
// (col<<17|pri) in high word), ballot compaction into zero-padded CSR storing
// BYTE OFFSETS (col*128), deg -> dis = rsqrt(deg), AND prep: g_x = half(dis ⊙ H).
// Resets g_cnt_raw. One warp per row, 8 rows per block.
__global__ void __launch_bounds__(256) dedup_k(const float* __restrict__ H) {
    __shared__ unsigned long long tbl[8][TBL];
    int wid  = threadIdx.x >> 5, lane = threadIdx.x & 31;
    int row  = blockIdx.x * 8 + wid;

    for (int i = lane; i < TBL; i += 32) tbl[wid][i] = 0ULL;
    __syncwarp();

    int k = g_cnt_raw[row];
    if (k > MAXK) k = MAXK;
    const uint2* src = &g_bucket[(size_t)row * MAXK];
    for (int t = lane; t < k; t += 32) {
        uint2 v = src[t];
        unsigned col = v.x >> 17;
        unsigned long long val = ((unsigned long long)v.x << 32) | (unsigned long long)v.y;
        unsigned h = col & (TBL - 1);
        while (true) {
            unsigned long long cur = tbl[wid][h];
            if (cur == 0ULL) {
                unsigned long long old = atomicCAS(&tbl[wid][h], 0ULL, val);
                if (old == 0ULL) break;
                cur = old;
            }
            if ((unsigned)(cur >> 49) == col) {       // same col -> keep max priority
                atomicMax(&tbl[wid][h], val);
                break;
            }
            h = (h + 1) & (TBL - 1);
        }
    }
    __syncwarp();

    // compact + degree sum; store byte offset col*128 (fp16 row = 128B)
    float deg = 0.f;
    int base = 0;
    uint2* dst = &g_adj[(size_t)row * MAXK];
    #pragma unroll
    for (int s0 = 0; s0 < TBL; s0 += 32) {
        unsigned long long cur = tbl[wid][s0 + lane];
        bool has = (cur != 0ULL);
        unsigned bal = __ballot_sync(0xFFFFFFFFu, has);
        if (has) {
            int pos = base + __popc(bal & ((1u << lane) - 1));
            unsigned col = ((unsigned)(cur >> 32)) >> 17;
            unsigned mb  = (unsigned)cur;
            dst[pos] = make_uint2(col << 7, mb);
            deg += __uint_as_float(mb);
        }
        base += __popc(bal);
    }
    // zero padding up to multiple of 8 (beyond stays zero from static init;
    // replays rewrite identical data so zero region is invariant)
    int pad = (base + 7) & ~7;
    if (base + lane < pad) dst[base + lane] = make_uint2(0u, 0u);

    // all-lanes deg reduction -> dis on every lane
    #pragma unroll
    for (int o = 16; o; o >>= 1) deg += __shfl_xor_sync(0xFFFFFFFFu, deg, o);
    float dis = rsqrtf(fmaxf(1.0f + deg, 1e-6f));

    // prep: g_x[row] = half(dis * H[row])
    const float2* Hrow = (const float2*)H + row * 32;
    float2 h2 = Hrow[lane];
    g_x[row * 32 + lane] = __floats2half2_rn(dis * h2.x, dis * h2.y);

    if (lane == 0) {
        g_nnz[row] = pad;
        g_dis[row] = dis;
        g_cnt_raw[row] = 0;     // ready for next replay
    }
}

// ---------------------------------------------------------------------------
// SpMM phase (R10 version): pre[row] = dis_r * (sum_e m_e*X~[col] + X~[row]).
// TWO rows per warp, interleaved in registers; 16 independent gathers + 8
// uniform LDG.128 in flight per warp. Pad entries are (0,0) -> w=0 no-ops.
// Output stored fp16 for the tensor-core GEMM.
__global__ void __launch_bounds__(256) spmm_k(int stage) {
    const __half2* Xin = (stage == 0) ? g_x : g_x1;
    int wid = threadIdx.x >> 5, lane = threadIdx.x & 31;
    int row0 = (blockIdx.x * 8 + wid) * 2;
    int row1 = row0 + 1;

    const char* XbL = (const char*)(Xin + (row0 & ~(NN - 1)) * 32) + lane * 4;
    float2 a0 = __half22float2(Xin[row0 * 32 + lane]);   // diag term X~row0
    float2 a1 = __half22float2(Xin[row1 * 32 + lane]);   // diag term X~row1
    const uint2* ar0 = &g_adj[(size_t)row0 * MAXK];
    const uint2* ar1 = ar0 + MAXK;
    int n = max(g_nnz[row0], g_nnz[row1]);               // <= MAXK, multiple of 8

    for (int k = 0; k < n; k += 8) {
        uint4 e0 = *(const uint4*)(ar0 + k);
        uint4 e1 = *(const uint4*)(ar0 + k + 2);
        uint4 e2 = *(const uint4*)(ar0 + k + 4);
        uint4 e3 = *(const uint4*)(ar0 + k + 6);
        uint4 g0 = *(const uint4*)(ar1 + k);
        uint4 g1 = *(const uint4*)(ar1 + k + 2);
        uint4 g2 = *(const uint4*)(ar1 + k + 4);
        uint4 g3 = *(const uint4*)(ar1 + k + 6);

        __half2 x0 = *(const __half2*)(XbL + e0.x);
        __half2 x1 = *(const __half2*)(XbL + e0.z);
        __half2 x2 = *(const __half2*)(XbL + e1.x);
        __half2 x3 = *(const __half2*)(XbL + e1.z);
        __half2 x4 = *(const __half2*)(XbL + e2.x);
        __half2 x5 = *(const __half2*)(XbL + e2.z);
        __half2 x6 = *(const __half2*)(XbL + e3.x);
        __half2 x7 = *(const __half2*)(XbL + e3.z);
        __half2 y0 = *(const __half2*)(XbL + g0.x);
        __half2 y1 = *(const __half2*)(XbL + g0.z);
        __half2 y2 = *(const __half2*)(XbL + g1.x);
        __half2 y3 = *(const __half2*)(XbL + g1.z);
        __half2 y4 = *(const __half2*)(XbL + g2.x);
        __half2 y5 = *(const __half2*)(XbL + g2.z);
        __half2 y6 = *(const __half2*)(XbL + g3.x);
        __half2 y7 = *(const __half2*)(XbL + g3.z);

        float2 f;
        f = __half22float2(x0); a0.x += __uint_as_float(e0.y) * f.x; a0.y += __uint_as_float(e0.y) * f.y;
        f = __half22float2(x1); a0.x += __uint_as_float(e0.w) * f.x; a0.y += __uint_as_float(e0.w) * f.y;
        f = __half22float2(x2); a0.x += __uint_as_float(e1.y) * f.x; a0.y += __uint_as_float(e1.y) * f.y;
        f = __half22float2(x3); a0.x += __uint_as_float(e1.w) * f.x; a0.y += __uint_as_float(e1.w) * f.y;
        f = __half22float2(x4); a0.x += __uint_as_float(e2.y) * f.x; a0.y += __uint_as_float(e2.y) * f.y;
        f = __half22float2(x5); a0.x += __uint_as_float(e2.w) * f.x; a0.y += __uint_as_float(e2.w) * f.y;
        f = __half22float2(x6); a0.x += __uint_as_float(e3.y) * f.x; a0.y += __uint_as_float(e3.y) * f.y;
        f = __half22float2(x7); a0.x += __uint_as_float(e3.w) * f.x; a0.y += __uint_as_float(e3.w) * f.y;
        f = __half22float2(y0); a1.x += __uint_as_float(g0.y) * f.x; a1.y += __uint_as_float(g0.y) * f.y;
        f = __half22float2(y1); a1.x += __uint_as_float(g0.w) * f.x; a1.y += __uint_as_float(g0.w) * f.y;
        f = __half22float2(y2); a1.x += __uint_as_float(g1.y) * f.x; a1.y += __uint_as_float(g1.y) * f.y;
        f = __half22float2(y3); a1.x += __uint_as_float(g1.w) * f.x; a1.y += __uint_as_float(g1.w) * f.y;
        f = __half22float2(y4); a1.x += __uint_as_float(g2.y) * f.x; a1.y += __uint_as_float(g2.y) * f.y;
        f = __half22float2(y5); a1.x += __uint_as_float(g2.w) * f.x; a1.y += __uint_as_float(g2.w) * f.y;
        f = __half22float2(y6); a1.x += __uint_as_float(g3.y) * f.x; a1.y += __uint_as_float(g3.y) * f.y;
        f = __half22float2(y7); a1.x += __uint_as_float(g3.w) * f.x; a1.y += __uint_as_float(g3.w) * f.y;
    }
    float d0 = g_dis[row0];
    float d1 = g_dis[row1];
    g_pre[row0 * 32 + lane] = __floats2half2_rn(d0 * a0.x, d0 * a0.y);
    g_pre[row1 * 32 + lane] = __floats2half2_rn(d1 * a1.x, d1 * a1.y);
}

// ---------------------------------------------------------------------------
// Tensor-core GEMM phase (R14 structure + chunk loop): v = pre @ W^T via wmma
// m16n16k16 (fp16 in, fp32 accum). W staged to smem ONCE per block, then the
// block loops over GCHUNKS consecutive 64-row chunks (grid 128 -> W staging
// and block fill/drain amortized 4x). Epilogue from fp32 smem tile:
// (stage 0) g_x1 = half(dis * gelu(v)); (stage 1) out = v (fp32).
__global__ void __launch_bounds__(256) gemm_k(const float* __restrict__ Wl,
                                              float* __restrict__ out,
                                              int stage) {
    __shared__ __half sWh[64 * 64];     // B: col-major (d,e), ld=64  (8 KB)
    __shared__ float  sOut[64 * 68];    // fp32 result tile, ld=68    (17 KB)
    int tid = threadIdx.x;
    int w = tid >> 5;

    for (int i = tid; i < 4096; i += 256)
        sWh[i] = __float2half(Wl[i]);

    for (int chunk = 0; chunk < GCHUNKS; chunk++) {
        int row0 = (blockIdx.x * GCHUNKS + chunk) * BR;
        const __half* A = (const __half*)g_pre + (size_t)row0 * 64;  // row-major ld=64

        __syncthreads();    // sWh ready (iter 0) / sOut fully consumed (iters 1+)

        #pragma unroll
        for (int j = 0; j < 2; j++) {
            int t = w * 2 + j;
            int tr = t >> 2, tc = t & 3;
            wmma::fragment<wmma::accumulator, 16, 16, 16, float> c;
            wmma::fill_fragment(c, 0.f);
            #pragma unroll
            for (int k0 = 0; k0 < 4; k0++) {
                wmma::fragment<wmma::matrix_a, 16, 16, 16, __half, wmma::row_major> a;
                wmma::fragment<wmma::matrix_b, 16, 16, 16, __half, wmma::col_major> b;
                wmma::load_matrix_sync(a, A + tr * 16 * 64 + k0 * 16, 64);
                wmma::load_matrix_sync(b, sWh + k0 * 16 + tc * 16 * 64, 64);
                wmma::mma_sync(c, a, b, c);
            }
            wmma::store_matrix_sync(&sOut[tr * 16 * 68 + tc * 16], c, 68,
                                    wmma::mem_row_major);
        }
        __syncthreads();

        // epilogue: 4 threads per row, 16 cols each
        int r = tid >> 2, c0 = (tid & 3) * 16;
        int row = row0 + r;
        const float* src = &sOut[r * 68 + c0];
        if (stage == 0) {
            float dis = g_dis[row];
            #pragma unroll
            for (int i = 0; i < 8; i++) {
                float vx = src[i * 2], vy = src[i * 2 + 1];
                vx = 0.5f * vx * (1.f + erff(vx * 0.70710678118654752f));
                vy = 0.5f * vy * (1.f + erff(vy * 0.70710678118654752f));
                g_x1[row * 32 + (c0 >> 1) + i] = __floats2half2_rn(dis * vx, dis * vy);
            }
        } else {
            float4* dst = (float4*)&out[(size_t)row * 64 + c0];
            #pragma unroll
            for (int i = 0; i < 4; i++)
                dst[i] = *(const float4*)&src[i * 4];
        }
    }
}

// ---------------------------------------------------------------------------
extern "C" void kernel_launch(void* const* d_in, const int* in_sizes, int n_in,
                              void* d_out, int out_size) {
    const float* H  = (const float*)d_in[0];
    const int*   ei = (const int*)  d_in[1];
    const float* m  = (const float*)d_in[2];
    const float* W  = (const float*)d_in[3];
    float* out = (float*)d_out;

    scatter_k<<<(BB * EE) / 256, 256>>>(ei, m);
    dedup_k<<<ROWS / 8, 256>>>(H);
    spmm_k<<<ROWS / 16, 256>>>(0);                             // g_x  -> g_pre
    gemm_k<<<ROWS / (BR * GCHUNKS), 256>>>(W, nullptr, 0);     // g_pre -> g_x1 (GELU)
    spmm_k<<<ROWS / 16, 256>>>(1);                             // g_x1 -> g_pre
    gemm_k<<<ROWS / (BR * GCHUNKS), 256>>>(W + DD * DD, out, 1); // g_pre -> out
}

// round 17
// speedup vs baseline: 1.4372x; 1.0751x over previous
#include <cuda_runtime.h>
#include <cuda_fp16.h>
#include <mma.h>
#include <math.h>

using namespace nvcuda;

// Problem constants (fixed-shape problem)
#define BB   16
#define NN   2048
#define DD   64
#define EE   32768
#define MAXK 128
#define ROWS (BB*NN)          // 32768
#define TBL  128
#define BR   64               // rows per layer block
#define LDP  72               // sPre leading dim (halves; mult of 8)

// Scratch (device globals; zero-initialized at module load; no allocation)
__device__ int      g_cnt_raw[ROWS];                 // scatter counters (reset by dedup)
__device__ int      g_nnz[ROWS];                     // padded row sizes (multiple of 8)
__device__ uint2    g_bucket[(size_t)ROWS * MAXK];   // 32 MB (col<<17|pri, m_bits)
__device__ float    g_dis[ROWS];
__device__ uint2    g_adj[(size_t)ROWS * MAXK];      // 32 MB (col<<7 byte-off, m_bits)
__device__ __half2  g_x [(size_t)ROWS * 32];         // 4 MB: dis ⊙ H   (layer 0 input)
__device__ __half2  g_x1[(size_t)ROWS * 32];         // 4 MB: dis ⊙ x1  (layer 1 input)

// ---------------------------------------------------------------------------
// scatter directed entries into per-row buckets, carrying m (coalesced read).
// key = (col << 17) | priority, priority = pass*E + e (pass2 > pass1)
__global__ void scatter_k(const int* __restrict__ ei, const float* __restrict__ m) {
    int t = blockIdx.x * blockDim.x + threadIdx.x;
    int b = t >> 15;
    int e = t & (EE - 1);
    int src = ei[b * 2 * EE + e];
    int dst = ei[b * 2 * EE + EE + e];
    unsigned mbits = __float_as_uint(m[t]);

    int r1 = b * NN + src;
    int p1 = atomicAdd(&g_cnt_raw[r1], 1);
    if (p1 < MAXK)
        g_bucket[(size_t)r1 * MAXK + p1] = make_uint2(((unsigned)dst << 17) | (unsigned)e, mbits);

    int r2 = b * NN + dst;
    int p2 = atomicAdd(&g_cnt_raw[r2], 1);
    if (p2 < MAXK)
        g_bucket[(size_t)r2 * MAXK + p2] = make_uint2(((unsigned)src << 17) | (unsigned)(EE + e), mbits);
}

// ---------------------------------------------------------------------------
// O(k) hash dedup (exact .set last-write-wins via 64-bit atomicMax on
// (col<<17|pri) in high word), ballot compaction into zero-padded CSR storing
// BYTE OFFSETS (col*128), deg -> dis = rsqrt(deg), AND prep: g_x = half(dis ⊙ H).
// Resets g_cnt_raw. One warp per row, 8 rows per block.
__global__ void __launch_bounds__(256) dedup_k(const float* __restrict__ H) {
    __shared__ unsigned long long tbl[8][TBL];
    int wid  = threadIdx.x >> 5, lane = threadIdx.x & 31;
    int row  = blockIdx.x * 8 + wid;

    for (int i = lane; i < TBL; i += 32) tbl[wid][i] = 0ULL;
    __syncwarp();

    int k = g_cnt_raw[row];
    if (k > MAXK) k = MAXK;
    const uint2* src = &g_bucket[(size_t)row * MAXK];
    for (int t = lane; t < k; t += 32) {
        uint2 v = src[t];
        unsigned col = v.x >> 17;
        unsigned long long val = ((unsigned long long)v.x << 32) | (unsigned long long)v.y;
        unsigned h = col & (TBL - 1);
        while (true) {
            unsigned long long cur = tbl[wid][h];
            if (cur == 0ULL) {
                unsigned long long old = atomicCAS(&tbl[wid][h], 0ULL, val);
                if (old == 0ULL) break;
                cur = old;
            }
            if ((unsigned)(cur >> 49) == col) {       // same col -> keep max priority
                atomicMax(&tbl[wid][h], val);
                break;
            }
            h = (h + 1) & (TBL - 1);
        }
    }
    __syncwarp();

    // compact + degree sum; store byte offset col*128 (fp16 row = 128B)
    float deg = 0.f;
    int base = 0;
    uint2* dst = &g_adj[(size_t)row * MAXK];
    #pragma unroll
    for (int s0 = 0; s0 < TBL; s0 += 32) {
        unsigned long long cur = tbl[wid][s0 + lane];
        bool has = (cur != 0ULL);
        unsigned bal = __ballot_sync(0xFFFFFFFFu, has);
        if (has) {
            int pos = base + __popc(bal & ((1u << lane) - 1));
            unsigned col = ((unsigned)(cur >> 32)) >> 17;
            unsigned mb  = (unsigned)cur;
            dst[pos] = make_uint2(col << 7, mb);
            deg += __uint_as_float(mb);
        }
        base += __popc(bal);
    }
    // zero padding up to multiple of 8 (beyond stays zero from static init;
    // replays rewrite identical data so zero region is invariant)
    int pad = (base + 7) & ~7;
    if (base + lane < pad) dst[base + lane] = make_uint2(0u, 0u);

    // all-lanes deg reduction -> dis on every lane
    #pragma unroll
    for (int o = 16; o; o >>= 1) deg += __shfl_xor_sync(0xFFFFFFFFu, deg, o);
    float dis = rsqrtf(fmaxf(1.0f + deg, 1e-6f));

    // prep: g_x[row] = half(dis * H[row])
    const float2* Hrow = (const float2*)H + row * 32;
    float2 h2 = Hrow[lane];
    g_x[row * 32 + lane] = __floats2half2_rn(dis * h2.x, dis * h2.y);

    if (lane == 0) {
        g_nnz[row] = pad;
        g_dis[row] = dis;
        g_cnt_raw[row] = 0;     // ready for next replay
    }
}

// ---------------------------------------------------------------------------
// Fused layer: SpMM (R10-style gather loop) -> pre in SMEM (fp16) ->
// tensor-core GEMM (R14 wmma structure, A from smem) -> epilogue.
// Block = 64 rows, 8 warps. No g_pre global roundtrip, one launch per layer.
//   pre[row] = dis_r * (sum_e m_e * X~[col] + X~[row])     (fp32 accum)
//   v = pre @ W^T  (wmma fp16 x fp16 -> fp32)
//   stage 0: g_x1 = half(dis * gelu(v)) ; stage 1: out = v (fp32)
__global__ void __launch_bounds__(256) layer_k(const float* __restrict__ Wl,
                                               float* __restrict__ out,
                                               int stage) {
    __shared__ __half sWh[64 * 64];      // B: col-major (d,e), ld=64   (8 KB)
    __shared__ __half sPre[64 * LDP];    // A: row-major, ld=LDP        (9 KB)
    __shared__ float  sOut[64 * 68];     // fp32 result tile, ld=68     (17 KB)

    const __half2* Xin = (stage == 0) ? g_x : g_x1;
    int tid = threadIdx.x;
    int w = tid >> 5, lane = tid & 31;
    int row0 = blockIdx.x * BR;

    // stage W
    for (int i = tid; i < 4096; i += 256)
        sWh[i] = __float2half(Wl[i]);

    // ---- SpMM phase: warp w owns rows row0 + w*8 .. +8, as 4 pairs ----
    int rbase = row0 + w * 8;
    const char* XbL = (const char*)(Xin + (row0 & ~(NN - 1)) * 32) + lane * 4;

    #pragma unroll
    for (int pr = 0; pr < 4; pr++) {
        int r0 = rbase + pr * 2;
        int r1 = r0 + 1;
        float2 a0 = __half22float2(Xin[r0 * 32 + lane]);   // diag term X~r0
        float2 a1 = __half22float2(Xin[r1 * 32 + lane]);   // diag term X~r1
        const uint2* ar0 = &g_adj[(size_t)r0 * MAXK];
        const uint2* ar1 = ar0 + MAXK;
        int n = max(g_nnz[r0], g_nnz[r1]);                 // multiple of 8

        for (int k = 0; k < n; k += 8) {
            uint4 e0 = *(const uint4*)(ar0 + k);
            uint4 e1 = *(const uint4*)(ar0 + k + 2);
            uint4 e2 = *(const uint4*)(ar0 + k + 4);
            uint4 e3 = *(const uint4*)(ar0 + k + 6);
            uint4 g0 = *(const uint4*)(ar1 + k);
            uint4 g1 = *(const uint4*)(ar1 + k + 2);
            uint4 g2 = *(const uint4*)(ar1 + k + 4);
            uint4 g3 = *(const uint4*)(ar1 + k + 6);

            __half2 x0 = *(const __half2*)(XbL + e0.x);
            __half2 x1 = *(const __half2*)(XbL + e0.z);
            __half2 x2 = *(const __half2*)(XbL + e1.x);
            __half2 x3 = *(const __half2*)(XbL + e1.z);
            __half2 x4 = *(const __half2*)(XbL + e2.x);
            __half2 x5 = *(const __half2*)(XbL + e2.z);
            __half2 x6 = *(const __half2*)(XbL + e3.x);
            __half2 x7 = *(const __half2*)(XbL + e3.z);
            __half2 y0 = *(const __half2*)(XbL + g0.x);
            __half2 y1 = *(const __half2*)(XbL + g0.z);
            __half2 y2 = *(const __half2*)(XbL + g1.x);
            __half2 y3 = *(const __half2*)(XbL + g1.z);
            __half2 y4 = *(const __half2*)(XbL + g2.x);
            __half2 y5 = *(const __half2*)(XbL + g2.z);
            __half2 y6 = *(const __half2*)(XbL + g3.x);
            __half2 y7 = *(const __half2*)(XbL + g3.z);

            float2 f;
            f = __half22float2(x0); a0.x += __uint_as_float(e0.y) * f.x; a0.y += __uint_as_float(e0.y) * f.y;
            f = __half22float2(x1); a0.x += __uint_as_float(e0.w) * f.x; a0.y += __uint_as_float(e0.w) * f.y;
            f = __half22float2(x2); a0.x += __uint_as_float(e1.y) * f.x; a0.y += __uint_as_float(e1.y) * f.y;
            f = __half22float2(x3); a0.x += __uint_as_float(e1.w) * f.x; a0.y += __uint_as_float(e1.w) * f.y;
            f = __half22float2(x4); a0.x += __uint_as_float(e2.y) * f.x; a0.y += __uint_as_float(e2.y) * f.y;
            f = __half22float2(x5); a0.x += __uint_as_float(e2.w) * f.x; a0.y += __uint_as_float(e2.w) * f.y;
            f = __half22float2(x6); a0.x += __uint_as_float(e3.y) * f.x; a0.y += __uint_as_float(e3.y) * f.y;
            f = __half22float2(x7); a0.x += __uint_as_float(e3.w) * f.x; a0.y += __uint_as_float(e3.w) * f.y;
            f = __half22float2(y0); a1.x += __uint_as_float(g0.y) * f.x; a1.y += __uint_as_float(g0.y) * f.y;
            f = __half22float2(y1); a1.x += __uint_as_float(g0.w) * f.x; a1.y += __uint_as_float(g0.w) * f.y;
            f = __half22float2(y2); a1.x += __uint_as_float(g1.y) * f.x; a1.y += __uint_as_float(g1.y) * f.y;
            f = __half22float2(y3); a1.x += __uint_as_float(g1.w) * f.x; a1.y += __uint_as_float(g1.w) * f.y;
            f = __half22float2(y4); a1.x += __uint_as_float(g2.y) * f.x; a1.y += __uint_as_float(g2.y) * f.y;
            f = __half22float2(y5); a1.x += __uint_as_float(g2.w) * f.x; a1.y += __uint_as_float(g2.w) * f.y;
            f = __half22float2(y6); a1.x += __uint_as_float(g3.y) * f.x; a1.y += __uint_as_float(g3.y) * f.y;
            f = __half22float2(y7); a1.x += __uint_as_float(g3.w) * f.x; a1.y += __uint_as_float(g3.w) * f.y;
        }
        float d0 = g_dis[r0];
        float d1 = g_dis[r1];
        int lr0 = r0 - row0, lr1 = r1 - row0;
        *(__half2*)&sPre[lr0 * LDP + lane * 2] = __floats2half2_rn(d0 * a0.x, d0 * a0.y);
        *(__half2*)&sPre[lr1 * LDP + lane * 2] = __floats2half2_rn(d1 * a1.x, d1 * a1.y);
    }
    __syncthreads();

    // ---- GEMM phase: wmma, A from smem (ld=LDP), B from smem (ld=64) ----
    #pragma unroll
    for (int j = 0; j < 2; j++) {
        int t = w * 2 + j;
        int tr = t >> 2, tc = t & 3;
        wmma::fragment<wmma::accumulator, 16, 16, 16, float> c;
        wmma::fill_fragment(c, 0.f);
        #pragma unroll
        for (int k0 = 0; k0 < 4; k0++) {
            wmma::fragment<wmma::matrix_a, 16, 16, 16, __half, wmma::row_major> a;
            wmma::fragment<wmma::matrix_b, 16, 16, 16, __half, wmma::col_major> b;
            wmma::load_matrix_sync(a, sPre + tr * 16 * LDP + k0 * 16, LDP);
            wmma::load_matrix_sync(b, sWh + k0 * 16 + tc * 16 * 64, 64);
            wmma::mma_sync(c, a, b, c);
        }
        wmma::store_matrix_sync(&sOut[tr * 16 * 68 + tc * 16], c, 68,
                                wmma::mem_row_major);
    }
    __syncthreads();

    // ---- epilogue: 4 threads per row, 16 cols each ----
    int r = tid >> 2, c0 = (tid & 3) * 16;
    int row = row0 + r;
    const float* src = &sOut[r * 68 + c0];
    if (stage == 0) {
        float dis = g_dis[row];
        #pragma unroll
        for (int i = 0; i < 8; i++) {
            float vx = src[i * 2], vy = src[i * 2 + 1];
            vx = 0.5f * vx * (1.f + erff(vx * 0.70710678118654752f));
            vy = 0.5f * vy * (1.f + erff(vy * 0.70710678118654752f));
            g_x1[row * 32 + (c0 >> 1) + i] = __floats2half2_rn(dis * vx, dis * vy);
        }
    } else {
        float4* dst = (float4*)&out[(size_t)row * 64 + c0];
        #pragma unroll
        for (int i = 0; i < 4; i++)
            dst[i] = *(const float4*)&src[i * 4];
    }
}

// ---------------------------------------------------------------------------
extern "C" void kernel_launch(void* const* d_in, const int* in_sizes, int n_in,
                              void* d_out, int out_size) {
    const float* H  = (const float*)d_in[0];
    const int*   ei = (const int*)  d_in[1];
    const float* m  = (const float*)d_in[2];
    const float* W  = (const float*)d_in[3];
    float* out = (float*)d_out;

    scatter_k<<<(BB * EE) / 256, 256>>>(ei, m);
    dedup_k<<<ROWS / 8, 256>>>(H);
    layer_k<<<ROWS / BR, 256>>>(W,           nullptr, 0);   // g_x  -> g_x1 (GELU)
    layer_k<<<ROWS / BR, 256>>>(W + DD * DD, out,     1);   // g_x1 -> out
}